// round 16
// baseline (speedup 1.0000x reference)
#include <cuda_runtime.h>
#include <cuda_fp16.h>
#include <stdint.h>

#define HID   32
#define LEN   32768
#define BATCH 16
#define KLCH  128

#define HSS 136     // hs row stride (fp32 words)
#define TS  20      // hT/xT row stride in u32 (40 half)

// smem u32 offsets
#define OF_W2   0       // 3072 : LVC W, per-shift frag order (half2)
#define OF_BIAS 3072    // 64 (fp32)
#define OF_CB   3136    // 32 (fp32)
#define OF_HS   3168    // 4352 : raw fp32 hidden tile (single buffer)
#define OF_HT   7520    // 3040 : hT[152][40 half]; rows 136..151 zero
#define OF_XT   10560   // 2600 : xT[130][40 half]
#define SMEM_U32 13160  // 52,640 B -> 4 CTA/SM (register-capped too)

// weights pre-packed per-shift (k=0..2), K=32, m16n8k16 B-frag order, half2-in-u32
__device__ __align__(16) uint32_t g_kth[(size_t)BATCH * KLCH * 3072];  // 25 MB
__device__ __align__(16) uint32_t g_w1h[1536];

__device__ __forceinline__ float fast_tanh(float x) { float r; asm("tanh.approx.f32 %0, %1;" : "=f"(r) : "f"(x)); return r; }
__device__ __forceinline__ float fast_ex2(float x)  { float r; asm("ex2.approx.f32 %0, %1;"  : "=f"(r) : "f"(x)); return r; }
__device__ __forceinline__ float fast_rcp(float x)  { float r; asm("rcp.approx.f32 %0, %1;"  : "=f"(r) : "f"(x)); return r; }
__device__ __forceinline__ float leaky(float x) { return (x >= 0.f) ? x : 0.2f * x; }

__device__ __forceinline__ uint32_t smem_u32p(const void* p) {
    uint32_t a; asm("{ .reg .u64 t; cvta.to.shared.u64 t, %1; cvt.u32.u64 %0, t; }" : "=r"(a) : "l"(p));
    return a;
}
__device__ __forceinline__ void cp_async16(uint32_t dst, const void* src, int src_bytes) {
    asm volatile("cp.async.ca.shared.global [%0], [%1], 16, %2;"
                 :: "r"(dst), "l"(src), "r"(src_bytes) : "memory");
}
__device__ __forceinline__ void mma_fp16(float c[4],
                                         uint32_t a0, uint32_t a1, uint32_t a2, uint32_t a3,
                                         uint32_t b0, uint32_t b1) {
    asm volatile(
        "mma.sync.aligned.m16n8k16.row.col.f32.f16.f16.f32 "
        "{%0,%1,%2,%3}, {%4,%5,%6,%7}, {%8,%9}, {%0,%1,%2,%3};"
        : "+f"(c[0]), "+f"(c[1]), "+f"(c[2]), "+f"(c[3])
        : "r"(a0), "r"(a1), "r"(a2), "r"(a3), "r"(b0), "r"(b1));
}
__device__ __forceinline__ void ldsm4(uint32_t* a, uint32_t addr) {
    asm volatile("ldmatrix.sync.aligned.m8n8.x4.shared.b16 {%0,%1,%2,%3}, [%4];"
                 : "=r"(a[0]), "=r"(a[1]), "=r"(a[2]), "=r"(a[3]) : "r"(addr));
}
__device__ __forceinline__ uint32_t packh2(float lo, float hi) {
    __half2 h = __floats2half2_rn(lo, hi);
    return *reinterpret_cast<uint32_t*>(&h);
}
__device__ __forceinline__ uint4 ldg_nc16(const uint4* p) {
    uint4 v;
    asm volatile("ld.global.nc.v4.u32 {%0,%1,%2,%3}, [%4];"
                 : "=r"(v.x), "=r"(v.y), "=r"(v.z), "=r"(v.w) : "l"(p));
    return v;
}
__device__ __forceinline__ void stg_cs(float* p, float v) {
    asm volatile("st.global.cs.f32 [%0], %1;" :: "l"(p), "f"(v) : "memory");
}

// ---------------------------------------------------------------------------
// Prep: kernel[b,i,o,k,l] -> g_kth[b][l][k*1024 + f2]  (per-shift B-frag order)
// Also (block 0,0,0) packs conv_w -> g_w1h[k*512 + f1].
// ---------------------------------------------------------------------------
__global__ void prep_weights(const float* __restrict__ kin,
                             const float* __restrict__ conv_w) {
    __shared__ uint32_t tile[32][33];
    int b  = blockIdx.z;
    int f0 = blockIdx.x * 32;
    int l0 = blockIdx.y * 32;
    int tx = threadIdx.x, ty = threadIdx.y;
    const float* src = kin + (size_t)b * 6144 * 128;
    uint32_t*    dst = g_kth + (size_t)b * 128 * 3072;
#pragma unroll
    for (int r = 0; r < 4; r++) {
        int f = f0 + ty + r * 8;
        int k = f >> 10, f2 = f & 1023;
        int j = f2 & 3, lane = (f2 >> 2) & 31, blk = f2 >> 7;  // blk = ks*4+q
        int q = blk & 3, ks = blk >> 2;
        int tq = lane & 3, tr = lane >> 2;
        int nt = 2 * q + (j >> 1), reg = j & 1;
        int o  = nt * 8 + tr;
        int ci0 = ks * 16 + 2 * tq + 8 * reg;
        int mlo = ci0 * 192 + o * 3 + k;
        int mhi = (ci0 + 1) * 192 + o * 3 + k;
        tile[ty + r * 8][tx] = packh2(src[(size_t)mlo * 128 + l0 + tx],
                                      src[(size_t)mhi * 128 + l0 + tx]);
    }
    __syncthreads();
#pragma unroll
    for (int r = 0; r < 4; r++) {
        int l = l0 + ty + r * 8;
        dst[(size_t)l * 3072 + f0 + tx] = tile[tx][ty + r * 8];
    }
    if (blockIdx.x == 0 && blockIdx.y == 0 && blockIdx.z == 0) {
        int t = ty * 32 + tx;
        for (int f = t; f < 1536; f += 256) {
            int k = f >> 9, f1 = f & 511;
            int j = f1 & 3, lane = (f1 >> 2) & 31, blk = f1 >> 7;  // blk = ks*2+q
            int q = blk & 1, ks = blk >> 1;
            int tq = lane & 3, tr = lane >> 2;
            int nt = 2 * q + (j >> 1), reg = j & 1;
            int co = nt * 8 + tr;
            int ci0 = ks * 16 + 2 * tq + 8 * reg;
            g_w1h[f] = packh2(conv_w[co * 96 + 3 * ci0 + k],
                              conv_w[co * 96 + 3 * (ci0 + 1) + k]);
        }
    }
}

// ---------------------------------------------------------------------------
// Main fused kernel: one CTA per (256-position chunk, batch); 2 pipelined subs.
// ---------------------------------------------------------------------------
__global__ __launch_bounds__(256, 4)
void lvc_mma_kernel(const float* __restrict__ hidden,
                    const float* __restrict__ bias,
                    const float* __restrict__ conv_w,
                    const float* __restrict__ conv_b,
                    float* __restrict__ out) {
    extern __shared__ float sm[];
    uint32_t* w2u   = (uint32_t*)(sm + OF_W2);
    float*    biasS = sm + OF_BIAS;
    float*    cbS   = sm + OF_CB;
    float*    hsf   = sm + OF_HS;
    uint32_t* hTu   = (uint32_t*)(sm + OF_HT);
    uint32_t* xTu   = (uint32_t*)(sm + OF_XT);

    const int tid  = threadIdx.x;
    const int wid  = tid >> 5;
    const int lane = tid & 31;
    const int l    = blockIdx.x;
    const int b    = blockIdx.y;
    const float* hidB = hidden + (size_t)b * HID * LEN;
    const uint32_t hb = smem_u32p(hsf);
    const uint32_t w2b = smem_u32p(w2u);

    // ---- group 0: prefetch sub0's hs tile (raw fp32) ----
    {
        const int s0p = l * 256;
        for (int idx = tid; idx < 1088; idx += 256) {
            int c = idx / 34, gr = idx - c * 34;
            int g = s0p - 4 + gr * 4;
            bool in = (g >= 0) && (g + 4 <= LEN);
            const float* src = hidB + (size_t)c * LEN + (in ? g : 0);
            cp_async16(hb + (uint32_t)(c * HSS + gr * 4) * 4, src, in ? 16 : 0);
        }
        asm volatile("cp.async.commit_group;" ::: "memory");
    }
    // ---- group 1: stage w2 via cp.async (overlaps P1 + stage-1) ----
    {
        const uint4* w2s = (const uint4*)(g_kth + ((size_t)b * KLCH + l) * 3072);
        for (int i = tid; i < 768; i += 256)
            cp_async16(w2b + (uint32_t)i * 16, w2s + i, 16);
        asm volatile("cp.async.commit_group;" ::: "memory");
        for (int i = tid; i < 320; i += 256) hTu[2720 + i] = 0;   // hT pad rows
    }
    if (tid < 64) biasS[tid] = bias[((size_t)b * 64 + tid) * KLCH + l];
    if (tid < 32) cbS[tid]   = conv_b[tid];

    const int tq = lane & 3;
    const int tr = lane >> 2;
    const int m0 = wid * 16;          // stage-1 m-tile
    const int mt2 = wid & 3;          // stage-2: 32-row block
    const int nh  = wid >> 2;         // stage-2: n-half (q parity)

    // P1 diagonal transpose mapping (conflict-free loads AND stores)
    const int ceP = tid & 15;
    const int g2P = tid >> 4;

    // ldmatrix lane base addresses (row = lane&15, col-u32 = (lane>>4)*4)
    const uint32_t hT_lane = smem_u32p(hTu) + (uint32_t)(((lane & 15) * TS + (lane >> 4) * 4) * 4);
    const uint32_t xT_lane = smem_u32p(xTu) + (uint32_t)(((lane & 15) * TS + (lane >> 4) * 4) * 4);

    const uint4* w1g = (const uint4*)g_w1h;   // stage-1 B from global (L1-resident)

#pragma unroll
    for (int s = 0; s < 2; s++) {
        const int s0 = l * 256 + s * 128;

        // s==0: need hs(g0); w2(g1) may still be in flight. s==1: need all.
        if (s == 0) asm volatile("cp.async.wait_group 1;" ::: "memory");
        else        asm volatile("cp.async.wait_group 0;" ::: "memory");
        __syncthreads();

        // ---- P1: build hT — diagonal float2 transpose, conflict-free ----
#pragma unroll
        for (int it = 0; it < 5; it++) {
            int vp = it * 16 + g2P + ceP;
            if (vp >= 80) vp -= 80;
            if (vp < 68) {
                float2 lo2 = *(const float2*)(hsf + (2 * ceP)     * HSS + 2 * vp);
                float2 hi2 = *(const float2*)(hsf + (2 * ceP + 1) * HSS + 2 * vp);
                hTu[(2 * vp)     * TS + ceP] = packh2(leaky(lo2.x), leaky(hi2.x));
                hTu[(2 * vp + 1) * TS + ceP] = packh2(leaky(lo2.y), leaky(hi2.y));
            }
        }
        __syncthreads();   // hT complete AND hs reads complete

        // hs is dead: group 2 = prefetch next sub's tile into the same buffer
        if (s == 0) {
            const int s0p = l * 256 + 128;
            for (int idx = tid; idx < 1088; idx += 256) {
                int c = idx / 34, gr = idx - c * 34;
                int g = s0p - 4 + gr * 4;
                bool in = (g >= 0) && (g + 4 <= LEN);
                const float* src = hidB + (size_t)c * LEN + (in ? g : 0);
                cp_async16(hb + (uint32_t)(c * HSS + gr * 4) * 4, src, in ? 16 : 0);
            }
            asm volatile("cp.async.commit_group;" ::: "memory");
        }

        // ---- P2: stage-1 shift-GEMM: 16m x 32n per warp, ldmatrix A ----
        float c1[4][4];
#pragma unroll
        for (int nt = 0; nt < 4; nt++)
#pragma unroll
            for (int j = 0; j < 4; j++) c1[nt][j] = 0.f;

#pragma unroll
        for (int k = 0; k < 3; k++) {
#pragma unroll
            for (int ks = 0; ks < 2; ks++) {
                uint32_t A[4];
                ldsm4(A, hT_lane + (uint32_t)(((m0 + 3 * k) * TS + ks * 8) * 4));
                uint4 q0 = ldg_nc16(w1g + k * 128 + ks * 64 + lane);
                uint4 q1 = ldg_nc16(w1g + k * 128 + ks * 64 + 32 + lane);
                mma_fp16(c1[0], A[0], A[1], A[2], A[3], q0.x, q0.y);
                mma_fp16(c1[1], A[0], A[1], A[2], A[3], q0.z, q0.w);
                mma_fp16(c1[2], A[0], A[1], A[2], A[3], q1.x, q1.y);
                mma_fp16(c1[3], A[0], A[1], A[2], A[3], q1.z, q1.w);
            }
        }

        // ---- P3: write xT — paired u32 stores, conflict-free ----
        {
            const int u = m0 + tr;
            const bool z0 = (s0 == 0) && (u == 0);
#pragma unroll
            for (int nt = 0; nt < 4; nt++) {
                int c  = nt * 8 + 2 * tq;
                int cw = nt * 4 + tq;
                float bA = cbS[c], bB = cbS[c + 1];
                uint32_t wlo = packh2(leaky(c1[nt][0] + bA), leaky(c1[nt][1] + bB));
                uint32_t whi = packh2(leaky(c1[nt][2] + bA), leaky(c1[nt][3] + bB));
                xTu[u * TS + cw]       = z0 ? 0u : wlo;
                xTu[(u + 8) * TS + cw] = whi;
            }
        }
        // tail rows u = 128,129 via an extra MMA tile on warp 0
        if (wid == 0) {
            float c1b[4][4];
#pragma unroll
            for (int nt = 0; nt < 4; nt++)
#pragma unroll
                for (int j = 0; j < 4; j++) c1b[nt][j] = 0.f;
#pragma unroll
            for (int k = 0; k < 3; k++) {
#pragma unroll
                for (int ks = 0; ks < 2; ks++) {
                    uint32_t A[4];
                    ldsm4(A, hT_lane + (uint32_t)(((128 + 3 * k) * TS + ks * 8) * 4));
                    uint4 q0 = ldg_nc16(w1g + k * 128 + ks * 64 + lane);
                    uint4 q1 = ldg_nc16(w1g + k * 128 + ks * 64 + 32 + lane);
                    mma_fp16(c1b[0], A[0], A[1], A[2], A[3], q0.x, q0.y);
                    mma_fp16(c1b[1], A[0], A[1], A[2], A[3], q0.z, q0.w);
                    mma_fp16(c1b[2], A[0], A[1], A[2], A[3], q1.x, q1.y);
                    mma_fp16(c1b[3], A[0], A[1], A[2], A[3], q1.z, q1.w);
                }
            }
            if (tr < 2) {
                int u = 128 + tr;               // p = s0 + 127 + tr
                bool ok = (s0 + 127 + tr) < LEN;
#pragma unroll
                for (int nt = 0; nt < 4; nt++) {
                    int c  = nt * 8 + 2 * tq;
                    uint32_t w = packh2(leaky(c1b[nt][0] + cbS[c]),
                                        leaky(c1b[nt][1] + cbS[c + 1]));
                    xTu[u * TS + nt * 4 + tq] = ok ? w : 0u;
                }
            }
        }
        // first sub: make sure w2 (group 1) has landed before stage-2 reads it
        if (s == 0) asm volatile("cp.async.wait_group 1;" ::: "memory");
        __syncthreads();

        // ---- P4: stage-2 shift-GEMM: 32m x 32n per warp (q-parity n-split) ----
        float c2[2][4][4];
#pragma unroll
        for (int mt = 0; mt < 2; mt++)
#pragma unroll
            for (int ni = 0; ni < 4; ni++)
#pragma unroll
                for (int j = 0; j < 4; j++) c2[mt][ni][j] = 0.f;

        const uint4* w2q = (const uint4*)w2u;
        const uint32_t xT_warp = xT_lane + (uint32_t)(mt2 * 32 * TS * 4);
#pragma unroll
        for (int k = 0; k < 3; k++) {
#pragma unroll
            for (int ks = 0; ks < 2; ks++) {
                uint32_t A0[4], A1[4];
                ldsm4(A0, xT_warp + (uint32_t)((k * TS + ks * 8) * 4));
                ldsm4(A1, xT_warp + (uint32_t)(((16 + k) * TS + ks * 8) * 4));
                uint4 qa = w2q[k * 256 + ks * 128 + nh * 32 + lane];        // nt 2nh, 2nh+1
                uint4 qb = w2q[k * 256 + ks * 128 + (nh + 2) * 32 + lane];  // nt 2nh+4, 2nh+5
                mma_fp16(c2[0][0], A0[0], A0[1], A0[2], A0[3], qa.x, qa.y);
                mma_fp16(c2[0][1], A0[0], A0[1], A0[2], A0[3], qa.z, qa.w);
                mma_fp16(c2[0][2], A0[0], A0[1], A0[2], A0[3], qb.x, qb.y);
                mma_fp16(c2[0][3], A0[0], A0[1], A0[2], A0[3], qb.z, qb.w);
                mma_fp16(c2[1][0], A1[0], A1[1], A1[2], A1[3], qa.x, qa.y);
                mma_fp16(c2[1][1], A1[0], A1[1], A1[2], A1[3], qa.z, qa.w);
                mma_fp16(c2[1][2], A1[0], A1[1], A1[2], A1[3], qb.x, qb.y);
                mma_fp16(c2[1][3], A1[0], A1[1], A1[2], A1[3], qb.z, qb.w);
            }
        }

        // ---- epilogue: gate + residual (half2 residual loads, streaming stores) ----
        {
            float* outB = out + (size_t)b * HID * LEN;
            const __half2* hT2 = (const __half2*)hTu;
            const float LOG2E = 1.4426950408889634f;
#pragma unroll
            for (int mt = 0; mt < 2; mt++) {
#pragma unroll
                for (int ni = 0; ni < 2; ni++) {
                    int obase = (2 * nh + ni) * 8 + 2 * tq;   // even channel
#pragma unroll
                    for (int jp = 0; jp < 2; jp++) {          // j = 2jp, 2jp+1
                        int m = mt2 * 32 + mt * 16 + tr + (jp << 3);
                        // residual pair: channels (obase, obase+1) at position m
                        float2 rp = __half22float2(hT2[(m + 4) * TS + (obase >> 1)]);
                        float r0 = (rp.x >= 0.f) ? rp.x : 5.f * rp.x;
                        float r1 = (rp.y >= 0.f) ? rp.y : 5.f * rp.y;
                        float gv0 = c2[mt][ni][2 * jp]         + biasS[obase];
                        float gv1 = c2[mt][ni][2 * jp + 1]     + biasS[obase + 1];
                        float hv0 = c2[mt][ni + 2][2 * jp]     + biasS[obase + 32];
                        float hv1 = c2[mt][ni + 2][2 * jp + 1] + biasS[obase + 33];
                        float sig0 = fast_rcp(1.f + fast_ex2(-LOG2E * gv0));
                        float sig1 = fast_rcp(1.f + fast_ex2(-LOG2E * gv1));
                        stg_cs(outB + (size_t)obase * LEN + s0 + m,
                               r0 + sig0 * fast_tanh(hv0));
                        stg_cs(outB + (size_t)(obase + 1) * LEN + s0 + m,
                               r1 + sig1 * fast_tanh(hv1));
                    }
                }
            }
        }
    }
}

// ---------------------------------------------------------------------------
extern "C" void kernel_launch(void* const* d_in, const int* in_sizes, int n_in,
                              void* d_out, int out_size) {
    const float* hidden = (const float*)d_in[0];
    const float* kern   = (const float*)d_in[1];
    const float* bias   = (const float*)d_in[2];
    const float* conv_w = (const float*)d_in[3];
    const float* conv_b = (const float*)d_in[4];
    float* out = (float*)d_out;

    prep_weights<<<dim3(96, 4, 16), dim3(32, 8)>>>(kern, conv_w);

    int smem_bytes = SMEM_U32 * 4;   // 52,640 B
    cudaFuncSetAttribute(lvc_mma_kernel,
                         cudaFuncAttributeMaxDynamicSharedMemorySize, smem_bytes);
    lvc_mma_kernel<<<dim3(KLCH, BATCH), 256, smem_bytes>>>(hidden, bias, conv_w, conv_b, out);
}

// round 17
// speedup vs baseline: 1.0556x; 1.0556x over previous
#include <cuda_runtime.h>
#include <cuda_fp16.h>
#include <stdint.h>

#define HID   32
#define LEN   32768
#define BATCH 16
#define KLCH  128

#define HSS 136     // hs row stride (fp32 words)
#define TS  20      // hT/xT row stride in u32 (40 half)

// smem u32 offsets
#define OF_W2   0       // 3072 : LVC W, per-shift frag order (half2)
#define OF_BIAS 3072    // 64 (fp32)
#define OF_CB   3136    // 32 (fp32)
#define OF_HS   3168    // 4352 : raw fp32 hidden tile (single buffer)
#define OF_HT   7520    // 3040 : hT[152][40 half]; rows 136..151 zero
#define OF_XT   10560   // 2600 : xT[130][40 half]
#define SMEM_U32 13160  // 52,640 B -> 4 CTA/SM (register-capped too)

// weights pre-packed per-shift (k=0..2), K=32, m16n8k16 B-frag order, half2-in-u32
__device__ __align__(16) uint32_t g_kth[(size_t)BATCH * KLCH * 3072];  // 25 MB
__device__ __align__(16) uint32_t g_w1h[1536];

__device__ __forceinline__ float fast_tanh(float x) { float r; asm("tanh.approx.f32 %0, %1;" : "=f"(r) : "f"(x)); return r; }
__device__ __forceinline__ float leaky(float x) { return (x >= 0.f) ? x : 0.2f * x; }

__device__ __forceinline__ uint32_t smem_u32p(const void* p) {
    uint32_t a; asm("{ .reg .u64 t; cvta.to.shared.u64 t, %1; cvt.u32.u64 %0, t; }" : "=r"(a) : "l"(p));
    return a;
}
__device__ __forceinline__ void cp_async16(uint32_t dst, const void* src, int src_bytes) {
    asm volatile("cp.async.ca.shared.global [%0], [%1], 16, %2;"
                 :: "r"(dst), "l"(src), "r"(src_bytes) : "memory");
}
__device__ __forceinline__ void mma_fp16(float c[4],
                                         uint32_t a0, uint32_t a1, uint32_t a2, uint32_t a3,
                                         uint32_t b0, uint32_t b1) {
    asm volatile(
        "mma.sync.aligned.m16n8k16.row.col.f32.f16.f16.f32 "
        "{%0,%1,%2,%3}, {%4,%5,%6,%7}, {%8,%9}, {%0,%1,%2,%3};"
        : "+f"(c[0]), "+f"(c[1]), "+f"(c[2]), "+f"(c[3])
        : "r"(a0), "r"(a1), "r"(a2), "r"(a3), "r"(b0), "r"(b1));
}
__device__ __forceinline__ void ldsm4(uint32_t* a, uint32_t addr) {
    asm volatile("ldmatrix.sync.aligned.m8n8.x4.shared.b16 {%0,%1,%2,%3}, [%4];"
                 : "=r"(a[0]), "=r"(a[1]), "=r"(a[2]), "=r"(a[3]) : "r"(addr));
}
__device__ __forceinline__ uint32_t packh2(float lo, float hi) {
    __half2 h = __floats2half2_rn(lo, hi);
    return *reinterpret_cast<uint32_t*>(&h);
}

// ---------------------------------------------------------------------------
// Prep: kernel[b,i,o,k,l] -> g_kth[b][l][k*1024 + f2]  (per-shift B-frag order)
// Also (block 0,0,0) packs conv_w -> g_w1h[k*512 + f1].
// ---------------------------------------------------------------------------
__global__ void prep_weights(const float* __restrict__ kin,
                             const float* __restrict__ conv_w) {
    __shared__ uint32_t tile[32][33];
    int b  = blockIdx.z;
    int f0 = blockIdx.x * 32;
    int l0 = blockIdx.y * 32;
    int tx = threadIdx.x, ty = threadIdx.y;
    const float* src = kin + (size_t)b * 6144 * 128;
    uint32_t*    dst = g_kth + (size_t)b * 128 * 3072;
#pragma unroll
    for (int r = 0; r < 4; r++) {
        int f = f0 + ty + r * 8;
        int k = f >> 10, f2 = f & 1023;
        int j = f2 & 3, lane = (f2 >> 2) & 31, blk = f2 >> 7;  // blk = ks*4+q
        int q = blk & 3, ks = blk >> 2;
        int tq = lane & 3, tr = lane >> 2;
        int nt = 2 * q + (j >> 1), reg = j & 1;
        int o  = nt * 8 + tr;
        int ci0 = ks * 16 + 2 * tq + 8 * reg;
        int mlo = ci0 * 192 + o * 3 + k;
        int mhi = (ci0 + 1) * 192 + o * 3 + k;
        tile[ty + r * 8][tx] = packh2(src[(size_t)mlo * 128 + l0 + tx],
                                      src[(size_t)mhi * 128 + l0 + tx]);
    }
    __syncthreads();
#pragma unroll
    for (int r = 0; r < 4; r++) {
        int l = l0 + ty + r * 8;
        dst[(size_t)l * 3072 + f0 + tx] = tile[tx][ty + r * 8];
    }
    if (blockIdx.x == 0 && blockIdx.y == 0 && blockIdx.z == 0) {
        int t = ty * 32 + tx;
        for (int f = t; f < 1536; f += 256) {
            int k = f >> 9, f1 = f & 511;
            int j = f1 & 3, lane = (f1 >> 2) & 31, blk = f1 >> 7;  // blk = ks*2+q
            int q = blk & 1, ks = blk >> 1;
            int tq = lane & 3, tr = lane >> 2;
            int nt = 2 * q + (j >> 1), reg = j & 1;
            int co = nt * 8 + tr;
            int ci0 = ks * 16 + 2 * tq + 8 * reg;
            g_w1h[f] = packh2(conv_w[co * 96 + 3 * ci0 + k],
                              conv_w[co * 96 + 3 * (ci0 + 1) + k]);
        }
    }
}

// ---------------------------------------------------------------------------
// Main fused kernel: one CTA per (256-position chunk, batch); 2 pipelined subs.
// ---------------------------------------------------------------------------
__global__ __launch_bounds__(256, 4)
void lvc_mma_kernel(const float* __restrict__ hidden,
                    const float* __restrict__ bias,
                    const float* __restrict__ conv_w,
                    const float* __restrict__ conv_b,
                    float* __restrict__ out) {
    extern __shared__ float sm[];
    uint32_t* w2u   = (uint32_t*)(sm + OF_W2);
    float*    biasS = sm + OF_BIAS;
    float*    cbS   = sm + OF_CB;
    float*    hsf   = sm + OF_HS;
    uint32_t* hTu   = (uint32_t*)(sm + OF_HT);
    uint32_t* xTu   = (uint32_t*)(sm + OF_XT);
    const __half* hTh = (const __half*)hTu;

    const int tid  = threadIdx.x;
    const int wid  = tid >> 5;
    const int lane = tid & 31;
    const int l    = blockIdx.x;
    const int b    = blockIdx.y;
    const float* hidB = hidden + (size_t)b * HID * LEN;
    const uint32_t hb = smem_u32p(hsf);
    const uint32_t w2b = smem_u32p(w2u);

    // ---- group 0: prefetch sub0's hs tile (raw fp32) ----
    {
        const int s0p = l * 256;
        for (int idx = tid; idx < 1088; idx += 256) {
            int c = idx / 34, gr = idx - c * 34;
            int g = s0p - 4 + gr * 4;
            bool in = (g >= 0) && (g + 4 <= LEN);
            const float* src = hidB + (size_t)c * LEN + (in ? g : 0);
            cp_async16(hb + (uint32_t)(c * HSS + gr * 4) * 4, src, in ? 16 : 0);
        }
        asm volatile("cp.async.commit_group;" ::: "memory");
    }
    // ---- group 1: stage w2 via cp.async (overlaps P1 + stage-1) ----
    {
        const uint4* w2s = (const uint4*)(g_kth + ((size_t)b * KLCH + l) * 3072);
        for (int i = tid; i < 768; i += 256)
            cp_async16(w2b + (uint32_t)i * 16, w2s + i, 16);
        asm volatile("cp.async.commit_group;" ::: "memory");
        for (int i = tid; i < 320; i += 256) hTu[2720 + i] = 0;   // hT pad rows
    }
    if (tid < 64) biasS[tid] = bias[((size_t)b * 64 + tid) * KLCH + l];
    if (tid < 32) cbS[tid]   = conv_b[tid];

    const int tq = lane & 3;
    const int tr = lane >> 2;
    const int m0 = wid * 16;          // stage-1 m-tile
    const int mt2 = wid & 3;          // stage-2: 32-row block
    const int nh  = wid >> 2;         // stage-2: n-half (q parity)

    // P1 diagonal transpose mapping (conflict-free loads AND stores)
    const int ceP = tid & 15;
    const int g2P = tid >> 4;

    // ldmatrix lane base addresses (row = lane&15, col-u32 = (lane>>4)*4)
    const uint32_t hT_lane = smem_u32p(hTu) + (uint32_t)(((lane & 15) * TS + (lane >> 4) * 4) * 4);
    const uint32_t xT_lane = smem_u32p(xTu) + (uint32_t)(((lane & 15) * TS + (lane >> 4) * 4) * 4);

    const uint4* w1g = (const uint4*)g_w1h;   // stage-1 B from global (L1-resident)

#pragma unroll
    for (int s = 0; s < 2; s++) {
        const int s0 = l * 256 + s * 128;

        // s==0: need hs(g0); w2(g1) may still be in flight. s==1: need all.
        if (s == 0) asm volatile("cp.async.wait_group 1;" ::: "memory");
        else        asm volatile("cp.async.wait_group 0;" ::: "memory");
        __syncthreads();

        // ---- P1: build hT — diagonal float2 transpose, conflict-free ----
#pragma unroll
        for (int it = 0; it < 5; it++) {
            int vp = it * 16 + g2P + ceP;
            if (vp >= 80) vp -= 80;
            if (vp < 68) {
                float2 lo2 = *(const float2*)(hsf + (2 * ceP)     * HSS + 2 * vp);
                float2 hi2 = *(const float2*)(hsf + (2 * ceP + 1) * HSS + 2 * vp);
                hTu[(2 * vp)     * TS + ceP] = packh2(leaky(lo2.x), leaky(hi2.x));
                hTu[(2 * vp + 1) * TS + ceP] = packh2(leaky(lo2.y), leaky(hi2.y));
            }
        }
        __syncthreads();   // hT complete AND hs reads complete

        // hs is dead: group 2 = prefetch next sub's tile into the same buffer
        if (s == 0) {
            const int s0p = l * 256 + 128;
            for (int idx = tid; idx < 1088; idx += 256) {
                int c = idx / 34, gr = idx - c * 34;
                int g = s0p - 4 + gr * 4;
                bool in = (g >= 0) && (g + 4 <= LEN);
                const float* src = hidB + (size_t)c * LEN + (in ? g : 0);
                cp_async16(hb + (uint32_t)(c * HSS + gr * 4) * 4, src, in ? 16 : 0);
            }
            asm volatile("cp.async.commit_group;" ::: "memory");
        }

        // ---- P2: stage-1 shift-GEMM: 16m x 32n per warp, ldmatrix A ----
        float c1[4][4];
#pragma unroll
        for (int nt = 0; nt < 4; nt++)
#pragma unroll
            for (int j = 0; j < 4; j++) c1[nt][j] = 0.f;

#pragma unroll
        for (int k = 0; k < 3; k++) {
#pragma unroll
            for (int ks = 0; ks < 2; ks++) {
                uint32_t A[4];
                ldsm4(A, hT_lane + (uint32_t)(((m0 + 3 * k) * TS + ks * 8) * 4));
                uint4 q0 = w1g[k * 128 + ks * 64 + lane];
                uint4 q1 = w1g[k * 128 + ks * 64 + 32 + lane];
                mma_fp16(c1[0], A[0], A[1], A[2], A[3], q0.x, q0.y);
                mma_fp16(c1[1], A[0], A[1], A[2], A[3], q0.z, q0.w);
                mma_fp16(c1[2], A[0], A[1], A[2], A[3], q1.x, q1.y);
                mma_fp16(c1[3], A[0], A[1], A[2], A[3], q1.z, q1.w);
            }
        }

        // ---- P3: write xT — paired u32 stores, conflict-free ----
        {
            const int u = m0 + tr;
            const bool z0 = (s0 == 0) && (u == 0);
#pragma unroll
            for (int nt = 0; nt < 4; nt++) {
                int c  = nt * 8 + 2 * tq;
                int cw = nt * 4 + tq;
                float bA = cbS[c], bB = cbS[c + 1];
                uint32_t wlo = packh2(leaky(c1[nt][0] + bA), leaky(c1[nt][1] + bB));
                uint32_t whi = packh2(leaky(c1[nt][2] + bA), leaky(c1[nt][3] + bB));
                xTu[u * TS + cw]       = z0 ? 0u : wlo;
                xTu[(u + 8) * TS + cw] = whi;
            }
        }
        // tail rows u = 128,129 via an extra MMA tile on warp 0
        if (wid == 0) {
            float c1b[4][4];
#pragma unroll
            for (int nt = 0; nt < 4; nt++)
#pragma unroll
                for (int j = 0; j < 4; j++) c1b[nt][j] = 0.f;
#pragma unroll
            for (int k = 0; k < 3; k++) {
#pragma unroll
                for (int ks = 0; ks < 2; ks++) {
                    uint32_t A[4];
                    ldsm4(A, hT_lane + (uint32_t)(((128 + 3 * k) * TS + ks * 8) * 4));
                    uint4 q0 = w1g[k * 128 + ks * 64 + lane];
                    uint4 q1 = w1g[k * 128 + ks * 64 + 32 + lane];
                    mma_fp16(c1b[0], A[0], A[1], A[2], A[3], q0.x, q0.y);
                    mma_fp16(c1b[1], A[0], A[1], A[2], A[3], q0.z, q0.w);
                    mma_fp16(c1b[2], A[0], A[1], A[2], A[3], q1.x, q1.y);
                    mma_fp16(c1b[3], A[0], A[1], A[2], A[3], q1.z, q1.w);
                }
            }
            if (tr < 2) {
                int u = 128 + tr;               // p = s0 + 127 + tr
                bool ok = (s0 + 127 + tr) < LEN;
#pragma unroll
                for (int nt = 0; nt < 4; nt++) {
                    int c  = nt * 8 + 2 * tq;
                    uint32_t w = packh2(leaky(c1b[nt][0] + cbS[c]),
                                        leaky(c1b[nt][1] + cbS[c + 1]));
                    xTu[u * TS + nt * 4 + tq] = ok ? w : 0u;
                }
            }
        }
        // first sub: make sure w2 (group 1) has landed before stage-2 reads it
        if (s == 0) asm volatile("cp.async.wait_group 1;" ::: "memory");
        __syncthreads();

        // ---- P4: stage-2 shift-GEMM: 32m x 32n per warp (q-parity n-split) ----
        float c2[2][4][4];
#pragma unroll
        for (int mt = 0; mt < 2; mt++)
#pragma unroll
            for (int ni = 0; ni < 4; ni++)
#pragma unroll
                for (int j = 0; j < 4; j++) c2[mt][ni][j] = 0.f;

        const uint4* w2q = (const uint4*)w2u;
        const uint32_t xT_warp = xT_lane + (uint32_t)(mt2 * 32 * TS * 4);
#pragma unroll
        for (int k = 0; k < 3; k++) {
#pragma unroll
            for (int ks = 0; ks < 2; ks++) {
                uint32_t A0[4], A1[4];
                ldsm4(A0, xT_warp + (uint32_t)((k * TS + ks * 8) * 4));
                ldsm4(A1, xT_warp + (uint32_t)(((16 + k) * TS + ks * 8) * 4));
                uint4 qa = w2q[k * 256 + ks * 128 + nh * 32 + lane];        // nt 2nh, 2nh+1
                uint4 qb = w2q[k * 256 + ks * 128 + (nh + 2) * 32 + lane];  // nt 2nh+4, 2nh+5
                mma_fp16(c2[0][0], A0[0], A0[1], A0[2], A0[3], qa.x, qa.y);
                mma_fp16(c2[0][1], A0[0], A0[1], A0[2], A0[3], qa.z, qa.w);
                mma_fp16(c2[0][2], A0[0], A0[1], A0[2], A0[3], qb.x, qb.y);
                mma_fp16(c2[0][3], A0[0], A0[1], A0[2], A0[3], qb.z, qb.w);
                mma_fp16(c2[1][0], A1[0], A1[1], A1[2], A1[3], qa.x, qa.y);
                mma_fp16(c2[1][1], A1[0], A1[1], A1[2], A1[3], qa.z, qa.w);
                mma_fp16(c2[1][2], A1[0], A1[1], A1[2], A1[3], qb.x, qb.y);
                mma_fp16(c2[1][3], A1[0], A1[1], A1[2], A1[3], qb.z, qb.w);
            }
        }

        // ---- epilogue: gate + residual; sigmoid via tanh identity (1 MUFU) ----
        {
            float* outB = out + (size_t)b * HID * LEN;
#pragma unroll
            for (int mt = 0; mt < 2; mt++) {
#pragma unroll
                for (int ni = 0; ni < 2; ni++) {
                    int obase = (2 * nh + ni) * 8 + 2 * tq;
#pragma unroll
                    for (int j = 0; j < 4; j++) {
                        int oo = obase + (j & 1);
                        int m  = mt2 * 32 + mt * 16 + tr + ((j >> 1) << 3);
                        float gv = c2[mt][ni][j]     + biasS[oo];
                        float hv = c2[mt][ni + 2][j] + biasS[oo + 32];
                        float sig = fmaf(0.5f, fast_tanh(0.5f * gv), 0.5f);
                        float ry = __half2float(hTh[(m + 4) * 40 + oo]);
                        float res = (ry >= 0.f) ? ry : 5.f * ry;
                        outB[(size_t)oo * LEN + s0 + m] = res + sig * fast_tanh(hv);
                    }
                }
            }
        }
    }
}

// ---------------------------------------------------------------------------
extern "C" void kernel_launch(void* const* d_in, const int* in_sizes, int n_in,
                              void* d_out, int out_size) {
    const float* hidden = (const float*)d_in[0];
    const float* kern   = (const float*)d_in[1];
    const float* bias   = (const float*)d_in[2];
    const float* conv_w = (const float*)d_in[3];
    const float* conv_b = (const float*)d_in[4];
    float* out = (float*)d_out;

    prep_weights<<<dim3(96, 4, 16), dim3(32, 8)>>>(kern, conv_w);

    int smem_bytes = SMEM_U32 * 4;   // 52,640 B
    cudaFuncSetAttribute(lvc_mma_kernel,
                         cudaFuncAttributeMaxDynamicSharedMemorySize, smem_bytes);
    lvc_mma_kernel<<<dim3(KLCH, BATCH), 256, smem_bytes>>>(hidden, bias, conv_w, conv_b, out);
}